// round 4
// baseline (speedup 1.0000x reference)
#include <cuda_runtime.h>
#include <math.h>

#define BB 8
#define NN 4096
#define DD 1024
#define HH 1792

#define NCHU 224          // h-chunks (fused blocks)
#define HPERU 8           // 1792 / 224

// Scratch (allocation-free contract): __device__ globals.
__device__ float g_xbar[BB * DD];          // mean_n x[b,n,:]  (atomic-accumulated)
__device__ float g_upart[NCHU][BB * DD];   // partial Wq^T @ kbar per h-chunk
__device__ float g_u[BB * DD];             // reduced u
__device__ float g_c[BB];                  // bq . kbar  (atomic-accumulated)

// ---------------------------------------------------------------------------
// K0: zero the atomic-accumulated scratch (xbar, c).
__global__ void k_zero() {
    int i = blockIdx.x * blockDim.x + threadIdx.x;
    if (i < BB * DD) g_xbar[i] = 0.f;
    if (i < BB) g_c[i] = 0.f;
}

// ---------------------------------------------------------------------------
// K1: xbar[b,d] = (1/N) sum_n x[b,n,d]
// grid (NCHUNK, B), block 256. Thread t owns float4 #t of the 1024-wide row.
#define NCHUNK 64
__global__ void k_xbar(const float* __restrict__ x) {
    const int b = blockIdx.y;
    const int nper = NN / NCHUNK;                 // 64
    const int nbase = blockIdx.x * nper;
    const int t = threadIdx.x;                    // 0..255 -> float4 index
    const float4* xp = (const float4*)(x + (size_t)b * NN * DD);

    float4 acc = make_float4(0.f, 0.f, 0.f, 0.f);
    #pragma unroll 4
    for (int n = nbase; n < nbase + nper; n++) {
        float4 v = xp[(size_t)n * (DD / 4) + t];
        acc.x += v.x; acc.y += v.y; acc.z += v.z; acc.w += v.w;
    }
    const float invN = 1.0f / (float)NN;
    float* dst = g_xbar + b * DD + t * 4;
    atomicAdd(dst + 0, acc.x * invN);
    atomicAdd(dst + 1, acc.y * invN);
    atomicAdd(dst + 2, acc.z * invN);
    atomicAdd(dst + 3, acc.w * invN);
}

// ---------------------------------------------------------------------------
// K2 (fused): per block c, h in [8c, 8c+8):
//   phase 1: warp w computes kbar[b][h=8c+w] = Wk[h].xbar[b] + bk[h]  (smem)
//            + atomic c[b] += bq[h]*kbar  (spread: lane b does batch b)
//   phase 2: upart[c][b][d] = sum_hh Wq[8c+hh][d] * kbar[b][hh]
__global__ void __launch_bounds__(256) k_fused(const float* __restrict__ Wk,
                                               const float* __restrict__ bk,
                                               const float* __restrict__ Wq,
                                               const float* __restrict__ bq) {
    const int c = blockIdx.x;
    const int t = threadIdx.x;
    const int warp = t >> 5, lane = t & 31;
    const int hbase = c * HPERU;

    __shared__ float s_kb[HPERU][BB];

    // ---- phase 1 ----
    {
        const int h = hbase + warp;
        const float4* wk = (const float4*)(Wk + (size_t)h * DD);
        float4 wreg[8];
        #pragma unroll
        for (int i = 0; i < 8; i++) wreg[i] = __ldg(&wk[i * 32 + lane]);

        float acc[BB];
        #pragma unroll
        for (int b = 0; b < BB; b++) {
            const float4* xb = (const float4*)(g_xbar + b * DD);
            float s = 0.f;
            #pragma unroll
            for (int i = 0; i < 8; i++) {
                float4 xv = xb[i * 32 + lane];
                s += wreg[i].x * xv.x + wreg[i].y * xv.y
                   + wreg[i].z * xv.z + wreg[i].w * xv.w;
            }
            acc[b] = s;
        }
        // butterfly reduce: all lanes end with the full sum
        #pragma unroll
        for (int b = 0; b < BB; b++)
            #pragma unroll
            for (int o = 16; o > 0; o >>= 1)
                acc[b] += __shfl_xor_sync(0xffffffffu, acc[b], o);

        const float bkh = bk[h];
        if (lane < BB) {
            const float kb = acc[lane] + bkh;     // lane b holds kbar[b][h]
            s_kb[warp][lane] = kb;
            atomicAdd(&g_c[lane], bq[h] * kb);    // 8 distinct addresses/warp
        }
    }
    __syncthreads();

    // ---- phase 2 ----
    float4 acc[BB];
    #pragma unroll
    for (int b = 0; b < BB; b++) acc[b] = make_float4(0.f, 0.f, 0.f, 0.f);

    #pragma unroll
    for (int hh = 0; hh < HPERU; hh++) {
        const float4 w = ((const float4*)(Wq + (size_t)(hbase + hh) * DD))[t];
        #pragma unroll
        for (int b = 0; b < BB; b++) {
            const float kb = s_kb[hh][b];
            acc[b].x = fmaf(w.x, kb, acc[b].x);
            acc[b].y = fmaf(w.y, kb, acc[b].y);
            acc[b].z = fmaf(w.z, kb, acc[b].z);
            acc[b].w = fmaf(w.w, kb, acc[b].w);
        }
    }
    float4* dst = (float4*)(g_upart[c]);
    #pragma unroll
    for (int b = 0; b < BB; b++) dst[b * (DD / 4) + t] = acc[b];
}

// ---------------------------------------------------------------------------
// K3: u[i] = sum_c upart[c][i]  (7.3 MB, L2-hot)
__global__ void k_ured() {
    const int i = blockIdx.x * 256 + threadIdx.x;   // 0 .. BB*DD-1
    float s = 0.f;
    #pragma unroll 8
    for (int c = 0; c < NCHU; c++) s += g_upart[c][i];
    g_u[i] = s;
}

// ---------------------------------------------------------------------------
// K4: scores[r] = scale * (x[r,:] . u[b,:] + c[b]),  r = b*N + n
// Forward order (reverse traversal regressed in R3). One warp per row.
__global__ void k_scores(const float* __restrict__ x, float* __restrict__ out) {
    const int warp = threadIdx.x >> 5, lane = threadIdx.x & 31;
    const int r = blockIdx.x * 8 + warp;          // 0 .. B*N-1
    const int b = r >> 12;                        // N = 4096
    const float4* xp = (const float4*)(x + (size_t)r * DD);
    const float4* up = (const float4*)(g_u + b * DD);

    float acc = 0.f;
    #pragma unroll
    for (int i = 0; i < 8; i++) {
        float4 xv = xp[i * 32 + lane];
        float4 uv = up[i * 32 + lane];
        acc += xv.x * uv.x + xv.y * uv.y + xv.z * uv.z + xv.w * uv.w;
    }
    #pragma unroll
    for (int o = 16; o > 0; o >>= 1)
        acc += __shfl_down_sync(0xffffffffu, acc, o);

    if (lane == 0) {
        const float scale = rsqrtf((float)HH);
        out[r] = scale * (acc + g_c[b]);
    }
}

// ---------------------------------------------------------------------------
extern "C" void kernel_launch(void* const* d_in, const int* in_sizes, int n_in,
                              void* d_out, int out_size) {
    const float* x  = (const float*)d_in[0];   // [B, N, D] f32
    const float* Wq = (const float*)d_in[1];   // [H, D]    f32
    const float* bq = (const float*)d_in[2];   // [H]       f32
    const float* Wk = (const float*)d_in[3];   // [H, D]    f32
    const float* bk = (const float*)d_in[4];   // [H]       f32
    float* out = (float*)d_out;                // [B, N]    f32

    k_zero<<<(BB * DD) / 256, 256>>>();
    k_xbar<<<dim3(NCHUNK, BB), 256>>>(x);
    k_fused<<<NCHU, 256>>>(Wk, bk, Wq, bq);
    k_ured<<<(BB * DD) / 256, 256>>>();
    k_scores<<<(BB * NN) / 8, 256>>>(x, out);
}

// round 5
// speedup vs baseline: 1.1040x; 1.1040x over previous
#include <cuda_runtime.h>
#include <math.h>

#define BB 8
#define NN 4096
#define DD 1024
#define HH 1792

#define NCHU 224          // h-chunks (fused blocks)
#define HPERU 8           // 1792 / 224
#define CGRP 8            // partials summed per k_ured block
#define NCG (NCHU / CGRP) // 28 c-groups

// Scratch (allocation-free contract): __device__ globals.
__device__ float g_xbar[BB * DD];          // mean_n x[b,n,:]  (atomic-accumulated)
__device__ float g_upart[NCHU][BB * DD];   // partial Wq^T @ kbar per h-chunk
__device__ float g_u[BB * DD];             // reduced u (atomic-accumulated)
__device__ float g_c[BB];                  // bq . kbar  (atomic-accumulated)

// ---------------------------------------------------------------------------
// K0: zero the atomic-accumulated scratch (xbar, u, c).
__global__ void k_zero() {
    int i = blockIdx.x * blockDim.x + threadIdx.x;
    if (i < BB * DD) { g_xbar[i] = 0.f; g_u[i] = 0.f; }
    if (i < BB) g_c[i] = 0.f;
}

// ---------------------------------------------------------------------------
// K1: xbar[b,d] = (1/N) sum_n x[b,n,d]
// grid (NCHUNK, B), block 256. Thread t owns float4 #t of the 1024-wide row.
#define NCHUNK 64
__global__ void k_xbar(const float* __restrict__ x) {
    const int b = blockIdx.y;
    const int nper = NN / NCHUNK;                 // 64
    const int nbase = blockIdx.x * nper;
    const int t = threadIdx.x;                    // 0..255 -> float4 index
    const float4* xp = (const float4*)(x + (size_t)b * NN * DD);

    float4 acc = make_float4(0.f, 0.f, 0.f, 0.f);
    #pragma unroll 4
    for (int n = nbase; n < nbase + nper; n++) {
        float4 v = xp[(size_t)n * (DD / 4) + t];
        acc.x += v.x; acc.y += v.y; acc.z += v.z; acc.w += v.w;
    }
    const float invN = 1.0f / (float)NN;
    float* dst = g_xbar + b * DD + t * 4;
    atomicAdd(dst + 0, acc.x * invN);
    atomicAdd(dst + 1, acc.y * invN);
    atomicAdd(dst + 2, acc.z * invN);
    atomicAdd(dst + 3, acc.w * invN);
}

// ---------------------------------------------------------------------------
// K2 (fused): per block c, h in [8c, 8c+8):
//   phase 1: warp w computes kbar[b][h=8c+w] = Wk[h].xbar[b] + bk[h]  (smem)
//            + atomic c[b] += bq[h]*kbar  (lane b -> distinct address)
//   phase 2: upart[c][b][d] = sum_hh Wq[8c+hh][d] * kbar[b][hh]
__global__ void __launch_bounds__(256) k_fused(const float* __restrict__ Wk,
                                               const float* __restrict__ bk,
                                               const float* __restrict__ Wq,
                                               const float* __restrict__ bq) {
    const int c = blockIdx.x;
    const int t = threadIdx.x;
    const int warp = t >> 5, lane = t & 31;
    const int hbase = c * HPERU;

    __shared__ float s_kb[HPERU][BB];

    // ---- phase 1 ----
    {
        const int h = hbase + warp;
        const float4* wk = (const float4*)(Wk + (size_t)h * DD);
        float4 wreg[8];
        #pragma unroll
        for (int i = 0; i < 8; i++) wreg[i] = __ldg(&wk[i * 32 + lane]);

        float acc[BB];
        #pragma unroll
        for (int b = 0; b < BB; b++) {
            const float4* xb = (const float4*)(g_xbar + b * DD);
            float s = 0.f;
            #pragma unroll
            for (int i = 0; i < 8; i++) {
                float4 xv = xb[i * 32 + lane];
                s += wreg[i].x * xv.x + wreg[i].y * xv.y
                   + wreg[i].z * xv.z + wreg[i].w * xv.w;
            }
            acc[b] = s;
        }
        #pragma unroll
        for (int b = 0; b < BB; b++)
            #pragma unroll
            for (int o = 16; o > 0; o >>= 1)
                acc[b] += __shfl_xor_sync(0xffffffffu, acc[b], o);

        const float bkh = bk[h];
        if (lane < BB) {
            const float kb = acc[lane] + bkh;     // lane b holds kbar[b][h]
            s_kb[warp][lane] = kb;
            atomicAdd(&g_c[lane], bq[h] * kb);
        }
    }
    __syncthreads();

    // ---- phase 2 ----
    float4 acc[BB];
    #pragma unroll
    for (int b = 0; b < BB; b++) acc[b] = make_float4(0.f, 0.f, 0.f, 0.f);

    #pragma unroll
    for (int hh = 0; hh < HPERU; hh++) {
        const float4 w = ((const float4*)(Wq + (size_t)(hbase + hh) * DD))[t];
        #pragma unroll
        for (int b = 0; b < BB; b++) {
            const float kb = s_kb[hh][b];
            acc[b].x = fmaf(w.x, kb, acc[b].x);
            acc[b].y = fmaf(w.y, kb, acc[b].y);
            acc[b].z = fmaf(w.z, kb, acc[b].z);
            acc[b].w = fmaf(w.w, kb, acc[b].w);
        }
    }
    float4* dst = (float4*)(g_upart[c]);
    #pragma unroll
    for (int b = 0; b < BB; b++) dst[b * (DD / 4) + t] = acc[b];
}

// ---------------------------------------------------------------------------
// K3: u reduction, parallel over (i-strip, c-group).
// grid (8, 28) = 224 blocks. Block (ib, cg) sums partials cg*8..cg*8+7 over
// its 1024-float strip (thread owns one float4; loads are L2-hot, MLP=8),
// then atomically merges into g_u (28 adds/address — negligible contention).
__global__ void k_ured() {
    const int ib = blockIdx.x;                    // 0..7
    const int cbase = blockIdx.y * CGRP;          // 0,8,..,216
    const int f4 = ib * 256 + threadIdx.x;        // float4 index into [BB*DD)

    float4 s = make_float4(0.f, 0.f, 0.f, 0.f);
    #pragma unroll
    for (int j = 0; j < CGRP; j++) {
        float4 v = ((const float4*)(g_upart[cbase + j]))[f4];
        s.x += v.x; s.y += v.y; s.z += v.z; s.w += v.w;
    }
    float* dst = g_u + f4 * 4;
    atomicAdd(dst + 0, s.x);
    atomicAdd(dst + 1, s.y);
    atomicAdd(dst + 2, s.z);
    atomicAdd(dst + 3, s.w);
}

// ---------------------------------------------------------------------------
// K4: scores[r] = scale * (x[r,:] . u[b,:] + c[b]),  r = b*N + n
// Forward order. One warp per row, MLP=8.
__global__ void k_scores(const float* __restrict__ x, float* __restrict__ out) {
    const int warp = threadIdx.x >> 5, lane = threadIdx.x & 31;
    const int r = blockIdx.x * 8 + warp;          // 0 .. B*N-1
    const int b = r >> 12;                        // N = 4096
    const float4* xp = (const float4*)(x + (size_t)r * DD);
    const float4* up = (const float4*)(g_u + b * DD);

    float acc = 0.f;
    #pragma unroll
    for (int i = 0; i < 8; i++) {
        float4 xv = xp[i * 32 + lane];
        float4 uv = up[i * 32 + lane];
        acc += xv.x * uv.x + xv.y * uv.y + xv.z * uv.z + xv.w * uv.w;
    }
    #pragma unroll
    for (int o = 16; o > 0; o >>= 1)
        acc += __shfl_down_sync(0xffffffffu, acc, o);

    if (lane == 0) {
        const float scale = rsqrtf((float)HH);
        out[r] = scale * (acc + g_c[b]);
    }
}

// ---------------------------------------------------------------------------
extern "C" void kernel_launch(void* const* d_in, const int* in_sizes, int n_in,
                              void* d_out, int out_size) {
    const float* x  = (const float*)d_in[0];   // [B, N, D] f32
    const float* Wq = (const float*)d_in[1];   // [H, D]    f32
    const float* bq = (const float*)d_in[2];   // [H]       f32
    const float* Wk = (const float*)d_in[3];   // [H, D]    f32
    const float* bk = (const float*)d_in[4];   // [H]       f32
    float* out = (float*)d_out;                // [B, N]    f32

    k_zero<<<(BB * DD) / 256, 256>>>();
    k_xbar<<<dim3(NCHUNK, BB), 256>>>(x);
    k_fused<<<NCHU, 256>>>(Wk, bk, Wq, bq);
    k_ured<<<dim3(8, NCG), 256>>>();
    k_scores<<<(BB * NN) / 8, 256>>>(x, out);
}

// round 6
// speedup vs baseline: 1.1563x; 1.0474x over previous
#include <cuda_runtime.h>
#include <math.h>

#define BB 8
#define NN 4096
#define DD 1024
#define HH 1792

#define GRID 296          // 148 SMs x 2 CTAs (forced by launch_bounds)
#define TPB 256
#define NCHU 256          // h-chunks in phase B
#define HPERU 7           // 256 * 7 = 1792
#define CGRP 8            // partials per phase-C block
#define BLKS_PER_B 37     // 296 / 8 blocks per batch in phase A
#define ROWS_PER_BLK 111  // ceil(4096 / 37)

// Scratch (allocation-free contract): __device__ globals.
__device__ float g_xbar[BB * DD];          // mean_n x  (atomic-accumulated)
__device__ float g_upart[NCHU][BB * DD];   // partial Wq^T @ kbar
__device__ float g_u[BB * DD];             // reduced u (atomic-accumulated)
__device__ float g_c[BB];                  // bq . kbar (atomic-accumulated)
__device__ unsigned g_bar;                 // grid barrier counter

// ---------------------------------------------------------------------------
// K0: reset accumulators + barrier counter (runs before k_main each replay).
__global__ void k_zero() {
    int i = blockIdx.x * blockDim.x + threadIdx.x;
    if (i < BB * DD) { g_xbar[i] = 0.f; g_u[i] = 0.f; }
    if (i < BB) g_c[i] = 0.f;
    if (i == 0) g_bar = 0u;
}

// ---------------------------------------------------------------------------
// Software grid barrier. Safe: all GRID blocks are co-resident
// (launch_bounds(256,2) on 148 SMs). Release via threadfence before arrive;
// acquire via threadfence after the poll.
__device__ __forceinline__ void gridbar(unsigned target) {
    __syncthreads();
    if (threadIdx.x == 0) {
        __threadfence();
        atomicAdd(&g_bar, 1u);
        unsigned v;
        do {
            asm volatile("ld.volatile.global.u32 %0, [%1];"
                         : "=r"(v) : "l"(&g_bar));
            if (v < target) __nanosleep(64);
        } while (v < target);
        __threadfence();
    }
    __syncthreads();
}

// ---------------------------------------------------------------------------
__global__ void __launch_bounds__(TPB, 2)
k_main(const float* __restrict__ x,  const float* __restrict__ Wq,
       const float* __restrict__ bq, const float* __restrict__ Wk,
       const float* __restrict__ bk, float* __restrict__ out) {
    const int t = threadIdx.x;
    const int blk = blockIdx.x;
    const int warp = t >> 5, lane = t & 31;
    __shared__ float s_kb[HPERU][BB];

    // ===== Phase A: xbar[b,d] = (1/N) sum_n x[b,n,d] =====================
    {
        const int b = blk / BLKS_PER_B;            // 0..7
        const int c = blk % BLKS_PER_B;
        const int n0 = c * ROWS_PER_BLK;
        const int n1 = (n0 + ROWS_PER_BLK < NN) ? n0 + ROWS_PER_BLK : NN;
        const float4* xp = (const float4*)(x + (size_t)b * NN * DD);

        float4 acc = make_float4(0.f, 0.f, 0.f, 0.f);
        int n = n0;
        for (; n + 8 <= n1; n += 8) {
            #pragma unroll
            for (int j = 0; j < 8; j++) {
                float4 v = xp[(size_t)(n + j) * (DD / 4) + t];
                acc.x += v.x; acc.y += v.y; acc.z += v.z; acc.w += v.w;
            }
        }
        for (; n < n1; n++) {
            float4 v = xp[(size_t)n * (DD / 4) + t];
            acc.x += v.x; acc.y += v.y; acc.z += v.z; acc.w += v.w;
        }
        const float invN = 1.0f / (float)NN;
        float* dst = g_xbar + b * DD + t * 4;
        atomicAdd(dst + 0, acc.x * invN);
        atomicAdd(dst + 1, acc.y * invN);
        atomicAdd(dst + 2, acc.z * invN);
        atomicAdd(dst + 3, acc.w * invN);
    }
    gridbar(GRID);

    // ===== Phase B: kbar chunk (smem) + upart ============================
    if (blk < NCHU) {
        const int hbase = blk * HPERU;
        if (warp < HPERU) {
            const int h = hbase + warp;
            const float4* wk = (const float4*)(Wk + (size_t)h * DD);
            float4 wreg[8];
            #pragma unroll
            for (int i = 0; i < 8; i++) wreg[i] = wk[i * 32 + lane];

            float acc[BB];
            #pragma unroll
            for (int b = 0; b < BB; b++) {
                const float4* xb = (const float4*)(g_xbar + b * DD);
                float s = 0.f;
                #pragma unroll
                for (int i = 0; i < 8; i++) {
                    float4 xv = xb[i * 32 + lane];
                    s += wreg[i].x * xv.x + wreg[i].y * xv.y
                       + wreg[i].z * xv.z + wreg[i].w * xv.w;
                }
                acc[b] = s;
            }
            #pragma unroll
            for (int b = 0; b < BB; b++)
                #pragma unroll
                for (int o = 16; o > 0; o >>= 1)
                    acc[b] += __shfl_xor_sync(0xffffffffu, acc[b], o);

            if (lane < BB) {
                const float kb = acc[lane] + bk[h];  // lane b = kbar[b][h]
                s_kb[warp][lane] = kb;
                atomicAdd(&g_c[lane], bq[h] * kb);
            }
        }
        __syncthreads();

        float4 acc[BB];
        #pragma unroll
        for (int b = 0; b < BB; b++) acc[b] = make_float4(0.f, 0.f, 0.f, 0.f);
        #pragma unroll
        for (int hh = 0; hh < HPERU; hh++) {
            const float4 w = ((const float4*)(Wq + (size_t)(hbase + hh) * DD))[t];
            #pragma unroll
            for (int b = 0; b < BB; b++) {
                const float kb = s_kb[hh][b];
                acc[b].x = fmaf(w.x, kb, acc[b].x);
                acc[b].y = fmaf(w.y, kb, acc[b].y);
                acc[b].z = fmaf(w.z, kb, acc[b].z);
                acc[b].w = fmaf(w.w, kb, acc[b].w);
            }
        }
        float4* dst = (float4*)(g_upart[blk]);
        #pragma unroll
        for (int b = 0; b < BB; b++) dst[b * (DD / 4) + t] = acc[b];
    }
    gridbar(2u * GRID);

    // ===== Phase C: u = sum_c upart[c]  (L2-hot, same kernel) ============
    if (blk < NCHU) {                       // 256 blocks: 8 strips x 32 groups
        const int ib = blk & 7;
        const int cbase = (blk >> 3) * CGRP;
        const int f4 = ib * 256 + t;
        float4 s = make_float4(0.f, 0.f, 0.f, 0.f);
        #pragma unroll
        for (int j = 0; j < CGRP; j++) {
            float4 v = ((const float4*)(g_upart[cbase + j]))[f4];
            s.x += v.x; s.y += v.y; s.z += v.z; s.w += v.w;
        }
        float* dst = g_u + f4 * 4;
        atomicAdd(dst + 0, s.x);
        atomicAdd(dst + 1, s.y);
        atomicAdd(dst + 2, s.z);
        atomicAdd(dst + 3, s.w);
    }
    gridbar(3u * GRID);

    // ===== Phase D: scores[r] = scale * (x[r].u[b] + c[b]) ===============
    {
        const float scale = rsqrtf((float)HH);
        const int wglobal = blk * 8 + warp;          // 0..2367
        for (int r = wglobal; r < BB * NN; r += GRID * 8) {
            const int b = r >> 12;                   // N = 4096
            const float4* xp = (const float4*)(x + (size_t)r * DD);
            const float4* up = (const float4*)(g_u + b * DD);
            float acc = 0.f;
            #pragma unroll
            for (int i = 0; i < 8; i++) {
                float4 xv = xp[i * 32 + lane];
                float4 uv = up[i * 32 + lane];
                acc += xv.x * uv.x + xv.y * uv.y + xv.z * uv.z + xv.w * uv.w;
            }
            #pragma unroll
            for (int o = 16; o > 0; o >>= 1)
                acc += __shfl_down_sync(0xffffffffu, acc, o);
            if (lane == 0) out[r] = scale * (acc + g_c[b]);
        }
    }
}

// ---------------------------------------------------------------------------
extern "C" void kernel_launch(void* const* d_in, const int* in_sizes, int n_in,
                              void* d_out, int out_size) {
    const float* x  = (const float*)d_in[0];   // [B, N, D] f32
    const float* Wq = (const float*)d_in[1];   // [H, D]    f32
    const float* bq = (const float*)d_in[2];   // [H]       f32
    const float* Wk = (const float*)d_in[3];   // [H, D]    f32
    const float* bk = (const float*)d_in[4];   // [H]       f32
    float* out = (float*)d_out;                // [B, N]    f32

    k_zero<<<(BB * DD + TPB - 1) / TPB, TPB>>>();
    k_main<<<GRID, TPB>>>(x, Wq, bq, Wk, bk, out);
}